// round 1
// baseline (speedup 1.0000x reference)
#include <cuda_runtime.h>

namespace {
constexpr int kGroups  = 131072;       // 64 * 2048
constexpr int kThreads = 256;
constexpr int kBlocks  = kGroups / kThreads;  // 512
constexpr float kDT = 0.005f;
}

// scratch: [0..511] = per-block sum16 partials, [512..1023] = sum32 partials
__device__ double g_partials[2 * kBlocks];

__device__ __forceinline__ void mm3(const float* a, const float* b, float* c) {
#pragma unroll
    for (int i = 0; i < 3; i++) {
#pragma unroll
        for (int j = 0; j < 3; j++) {
            c[i*3+j] = fmaf(a[i*3+0], b[0+j], fmaf(a[i*3+1], b[3+j], a[i*3+2] * b[6+j]));
        }
    }
}

// R = exp(wedge(phi)), Rodrigues with small-angle branch (matches reference)
template <bool FAST>
__device__ __forceinline__ void so3_exp(float px, float py, float pz, float* R) {
    float n2 = fmaf(px, px, fmaf(py, py, pz * pz));
    if (n2 < 1e-14f) {           // angle < 1e-7
        R[0] = 1.f; R[1] = -pz; R[2] =  py;
        R[3] =  pz; R[4] = 1.f; R[5] = -px;
        R[6] = -py; R[7] =  px; R[8] = 1.f;
        return;
    }
    float ang = sqrtf(n2);
    float inv = 1.0f / ang;
    float ax = px * inv, ay = py * inv, az = pz * inv;
    float s, c;
    if (FAST) { __sincosf(ang, &s, &c); }
    else      { s = sinf(ang); c = cosf(ang); }
    float C = 1.0f - c;
    float Cxy = C * ax * ay, Cxz = C * ax * az, Cyz = C * ay * az;
    R[0] = fmaf(C * ax, ax, c);
    R[1] = Cxy - s * az;
    R[2] = Cxz + s * ay;
    R[3] = Cxy + s * az;
    R[4] = fmaf(C * ay, ay, c);
    R[5] = Cyz - s * ax;
    R[6] = Cxz - s * ay;
    R[7] = Cyz + s * ax;
    R[8] = fmaf(C * az, az, c);
}

// rs = so3_log(A^T B); returns sum over 3 comps of SmoothL1(rs / 0.005)
__device__ __forceinline__ float log_huber(const float* A, const float* B) {
    // M = A^T @ B : M[i][j] = sum_k A[k][i] * B[k][j]
    float m00 = fmaf(A[0], B[0], fmaf(A[3], B[3], A[6] * B[6]));
    float m11 = fmaf(A[1], B[1], fmaf(A[4], B[4], A[7] * B[7]));
    float m22 = fmaf(A[2], B[2], fmaf(A[5], B[5], A[8] * B[8]));
    float m01 = fmaf(A[0], B[1], fmaf(A[3], B[4], A[6] * B[7]));
    float m10 = fmaf(A[1], B[0], fmaf(A[4], B[3], A[7] * B[6]));
    float m02 = fmaf(A[0], B[2], fmaf(A[3], B[5], A[6] * B[8]));
    float m20 = fmaf(A[2], B[0], fmaf(A[5], B[3], A[8] * B[6]));
    float m12 = fmaf(A[1], B[2], fmaf(A[4], B[5], A[7] * B[8]));
    float m21 = fmaf(A[2], B[1], fmaf(A[5], B[4], A[8] * B[7]));

    float tr = m00 + m11 + m22;
    float ca = 0.5f * tr - 0.5f;
    ca = fminf(fmaxf(ca, -1.0f + 1e-7f), 1.0f - 1e-7f);
    float ang = acosf(ca);
    // after clamping, ang >= ~4.5e-4 > 1e-7 -> small branch of so3_log never taken
    float coef = 0.5f * ang / sinf(ang);
    float r0 = coef * (m21 - m12);
    float r1 = coef * (m02 - m20);
    float r2 = coef * (m10 - m01);

    float sum = 0.0f;
#pragma unroll
    for (int k = 0; k < 3; k++) {
        float r = (k == 0) ? r0 : ((k == 1) ? r1 : r2);
        float x = r * 200.0f;           // / HUBER
        float axv = fabsf(x);
        sum += (axv < 1.0f) ? (0.5f * x * x) : (axv - 0.5f);
    }
    return sum;
}

__global__ void __launch_bounds__(kThreads)
dg_loss_kernel(const float* __restrict__ w_hat, const float* __restrict__ dw16) {
    const int m = blockIdx.x * kThreads + threadIdx.x;   // group id, 0..131071
    const int g = m & 2047;                              // group index within batch row

    // ---- compose 16 predicted increments: acc = prod_{i=0..15} exp(DT * w_hat[i]) ----
    const float4* base = reinterpret_cast<const float4*>(w_hat) + (size_t)m * 12;
    float acc[9];
#pragma unroll
    for (int chunk = 0; chunk < 4; chunk++) {
        float4 q0 = base[chunk * 3 + 0];
        float4 q1 = base[chunk * 3 + 1];
        float4 q2 = base[chunk * 3 + 2];
        float f[12] = {q0.x, q0.y, q0.z, q0.w, q1.x, q1.y, q1.z, q1.w,
                       q2.x, q2.y, q2.z, q2.w};
#pragma unroll
        for (int i = 0; i < 4; i++) {
            float R[9];
            so3_exp<true>(kDT * f[3*i+0], kDT * f[3*i+1], kDT * f[3*i+2], R);
            if (chunk == 0 && i == 0) {
#pragma unroll
                for (int k = 0; k < 9; k++) acc[k] = R[k];
            } else {
                float t[9];
                mm3(acc, R, t);
#pragma unroll
                for (int k = 0; k < 9; k++) acc[k] = t[k];
            }
        }
    }

    // ---- ground-truth increment ----
    float4 d = reinterpret_cast<const float4*>(dw16)[(size_t)m * 12];
    float R16[9];
    so3_exp<false>(d.x, d.y, d.z, R16);

    // ---- 16-level loss term ----
    float s16 = 0.0f;
    if (g >= 5) s16 = log_huber(acc, R16);

    // ---- 32-level: pair adjacent groups via lane shuffle (lane parity == g parity) ----
    float accP[9], R16P[9];
#pragma unroll
    for (int k = 0; k < 9; k++) {
        accP[k] = __shfl_xor_sync(0xFFFFFFFFu, acc[k], 1);
        R16P[k] = __shfl_xor_sync(0xFFFFFFFFu, R16[k], 1);
    }
    float s32 = 0.0f;
    if (((g & 1) == 0) && g >= 10) {
        float dh[9], d32[9];
        mm3(acc, accP, dh);     // R[2p] @ R[2p+1]
        mm3(R16, R16P, d32);
        s32 = log_huber(dh, d32);
    }

    // ---- block reduction (deterministic, no atomics) ----
#pragma unroll
    for (int off = 16; off > 0; off >>= 1) {
        s16 += __shfl_down_sync(0xFFFFFFFFu, s16, off);
        s32 += __shfl_down_sync(0xFFFFFFFFu, s32, off);
    }
    __shared__ float w16[kThreads / 32], w32[kThreads / 32];
    int lane = threadIdx.x & 31, wid = threadIdx.x >> 5;
    if (lane == 0) { w16[wid] = s16; w32[wid] = s32; }
    __syncthreads();
    if (threadIdx.x == 0) {
        float a = 0.0f, b = 0.0f;
#pragma unroll
        for (int i = 0; i < kThreads / 32; i++) { a += w16[i]; b += w32[i]; }
        g_partials[blockIdx.x] = (double)a;
        g_partials[kBlocks + blockIdx.x] = (double)b;
    }
}

__global__ void __launch_bounds__(256)
dg_finalize_kernel(float* __restrict__ out) {
    __shared__ double sh16[256], sh32[256];
    int t = threadIdx.x;
    sh16[t] = g_partials[t] + g_partials[t + 256];
    sh32[t] = g_partials[kBlocks + t] + g_partials[kBlocks + t + 256];
    __syncthreads();
    for (int off = 128; off > 0; off >>= 1) {
        if (t < off) { sh16[t] += sh16[t + off]; sh32[t] += sh32[t + off]; }
        __syncthreads();
    }
    if (t == 0) {
        // W * HUBER^2 = 1e6 * 0.005^2 = 25
        // loss16 denom: 64*2043*3 = 392256
        // loss32 denom: 64*1019*3 = 195648, extra /4 -> 782592
        double l16 = 25.0 * sh16[0] / 392256.0;
        double l32 = 25.0 * sh32[0] / 782592.0;
        out[0] = (float)(l16 + l32);
    }
}

extern "C" void kernel_launch(void* const* d_in, const int* in_sizes, int n_in,
                              void* d_out, int out_size) {
    const float* w_hat = (const float*)d_in[0];
    const float* dw16  = (const float*)d_in[1];
    float* out = (float*)d_out;

    dg_loss_kernel<<<kBlocks, kThreads>>>(w_hat, dw16);
    dg_finalize_kernel<<<1, 256>>>(out);
}

// round 2
// speedup vs baseline: 1.2004x; 1.2004x over previous
#include <cuda_runtime.h>

namespace {
constexpr int kGroups  = 131072;       // 64 * 2048
constexpr int kThreads = 256;
constexpr int kBlocks  = kGroups / kThreads;  // 512
constexpr float kDT = 0.005f;
}

// [0..511] = per-block sum16 partials, [512..1023] = sum32 partials
__device__ double g_partials[2 * kBlocks];
__device__ unsigned int g_sync = 0;

// Hamilton product: q = a (x) b   (R(a (x) b) = R(a) R(b))
__device__ __forceinline__ void qmul(float aw, float ax, float ay, float az,
                                     float bw, float bx, float by, float bz,
                                     float& w, float& x, float& y, float& z) {
    w = aw*bw - ax*bx - ay*by - az*bz;
    x = aw*bx + ax*bw + ay*bz - az*by;
    y = aw*by - ax*bz + ay*bw + az*bx;
    z = aw*bz + ax*by - ay*bx + az*bw;
}

// exp of a SMALL rotation vector (|phi| <= ~0.05) as a unit quaternion.
// cos(h) and sin(h)/(2h) with h=|phi|/2 are even in h -> polynomials in n2,
// no sqrt / no sincos / no branch. Series error ~1e-12 at |phi|=0.05.
__device__ __forceinline__ void exp_quat_small(float px, float py, float pz,
                                               float& w, float& x, float& y, float& z) {
    float n2 = fmaf(px, px, fmaf(py, py, pz * pz));
    float h2 = 0.25f * n2;                      // (|phi|/2)^2
    w = 1.0f + h2 * (-0.5f + h2 * (1.0f / 24.0f));
    float s = 0.5f + h2 * (-1.0f / 12.0f + h2 * (1.0f / 240.0f)); // sin(h)/|phi|
    x = s * px; y = s * py; z = s * pz;
}

// rs = log( R(a)^T R(b) ) via q = conj(a) (x) b;  returns sum_k SmoothL1(rs_k/HUBER)
__device__ __forceinline__ float log_huber_q(float aw, float ax, float ay, float az,
                                             float bw, float bx, float by, float bz) {
    // conj(a) (x) b
    float w = aw*bw + ax*bx + ay*by + az*bz;
    float x = aw*bx - ax*bw - ay*bz + az*by;
    float y = aw*by + ax*bz - ay*bw - az*bx;
    float z = aw*bz - ax*by + ay*bx - az*bw;
    if (w < 0.0f) { w = -w; x = -x; y = -y; z = -z; }
    float n2 = fmaf(x, x, fmaf(y, y, z * z));
    float n  = sqrtf(n2);
    float ang = 2.0f * atan2f(n, w);            // in [0, pi]
    float coef = ang / fmaxf(n, 1e-20f);
    float r0 = coef * x, r1 = coef * y, r2 = coef * z;

    float sum = 0.0f;
#pragma unroll
    for (int k = 0; k < 3; k++) {
        float r = (k == 0) ? r0 : ((k == 1) ? r1 : r2);
        float xx = r * 200.0f;                  // / HUBER
        float axv = fabsf(xx);
        sum += (axv < 1.0f) ? (0.5f * xx * xx) : (axv - 0.5f);
    }
    return sum;
}

__global__ void __launch_bounds__(kThreads)
dg_loss_kernel(const float* __restrict__ w_hat, const float* __restrict__ dw16,
               float* __restrict__ out) {
    const int m = blockIdx.x * kThreads + threadIdx.x;   // group id, 0..131071
    const int g = m & 2047;                              // group index within batch row

    // ---- compose 16 predicted increments as a quaternion product ----
    const float4* base = reinterpret_cast<const float4*>(w_hat) + (size_t)m * 12;
    float qw, qx, qy, qz;
    {
        // load all 48 floats (12x LDG.128, front-batched)
        float f[48];
#pragma unroll
        for (int v = 0; v < 12; v++) {
            float4 q = base[v];
            f[4*v+0] = q.x; f[4*v+1] = q.y; f[4*v+2] = q.z; f[4*v+3] = q.w;
        }
        exp_quat_small(kDT * f[0], kDT * f[1], kDT * f[2], qw, qx, qy, qz);
#pragma unroll
        for (int i = 1; i < 16; i++) {
            float rw, rx, ry, rz;
            exp_quat_small(kDT * f[3*i+0], kDT * f[3*i+1], kDT * f[3*i+2], rw, rx, ry, rz);
            float tw, tx, ty, tz;
            qmul(qw, qx, qy, qz, rw, rx, ry, rz, tw, tx, ty, tz);
            qw = tw; qx = tx; qy = ty; qz = tz;
        }
    }

    // ---- ground-truth increment (full-range angle: precise sqrt + sincos) ----
    float pw, px, py, pz;
    {
        float4 d = reinterpret_cast<const float4*>(dw16)[(size_t)m * 12];
        float n2 = fmaf(d.x, d.x, fmaf(d.y, d.y, d.z * d.z));
        float th = sqrtf(n2);
        float s, c;
        sincosf(0.5f * th, &s, &c);
        float k = (th > 1e-7f) ? (s / th) : 0.5f;
        pw = c; px = k * d.x; py = k * d.y; pz = k * d.z;
    }

    // ---- 16-level loss term ----
    float s16 = (g >= 5) ? log_huber_q(qw, qx, qy, qz, pw, px, py, pz) : 0.0f;

    // ---- 32-level: pair adjacent groups via lane shuffle (lane parity == g parity) ----
    float qwP = __shfl_xor_sync(0xFFFFFFFFu, qw, 1);
    float qxP = __shfl_xor_sync(0xFFFFFFFFu, qx, 1);
    float qyP = __shfl_xor_sync(0xFFFFFFFFu, qy, 1);
    float qzP = __shfl_xor_sync(0xFFFFFFFFu, qz, 1);
    float pwP = __shfl_xor_sync(0xFFFFFFFFu, pw, 1);
    float pxP = __shfl_xor_sync(0xFFFFFFFFu, px, 1);
    float pyP = __shfl_xor_sync(0xFFFFFFFFu, py, 1);
    float pzP = __shfl_xor_sync(0xFFFFFFFFu, pz, 1);

    float s32 = 0.0f;
    if (((g & 1) == 0) && g >= 10) {
        float hw, hx, hy, hz, gw, gx, gy, gz;
        qmul(qw, qx, qy, qz, qwP, qxP, qyP, qzP, hw, hx, hy, hz);   // hat pair
        qmul(pw, px, py, pz, pwP, pxP, pyP, pzP, gw, gx, gy, gz);   // gt pair
        s32 = log_huber_q(hw, hx, hy, hz, gw, gx, gy, gz);
    }

    // ---- deterministic block reduction ----
#pragma unroll
    for (int off = 16; off > 0; off >>= 1) {
        s16 += __shfl_down_sync(0xFFFFFFFFu, s16, off);
        s32 += __shfl_down_sync(0xFFFFFFFFu, s32, off);
    }
    __shared__ float w16[kThreads / 32], w32[kThreads / 32];
    __shared__ double sa[kThreads], sb[kThreads];
    __shared__ bool isLast;
    int lane = threadIdx.x & 31, wid = threadIdx.x >> 5;
    if (lane == 0) { w16[wid] = s16; w32[wid] = s32; }
    __syncthreads();
    if (threadIdx.x == 0) {
        float a = 0.0f, b = 0.0f;
#pragma unroll
        for (int i = 0; i < kThreads / 32; i++) { a += w16[i]; b += w32[i]; }
        g_partials[blockIdx.x] = (double)a;
        g_partials[kBlocks + blockIdx.x] = (double)b;
        __threadfence();
        unsigned prev = atomicAdd(&g_sync, 1u);
        isLast = (prev == (unsigned)(kBlocks - 1));
    }
    __syncthreads();

    // ---- last block finishes: fixed-order sum => deterministic ----
    if (isLast) {
        __threadfence();
        int t = threadIdx.x;
        sa[t] = g_partials[t] + g_partials[t + 256];
        sb[t] = g_partials[kBlocks + t] + g_partials[kBlocks + t + 256];
        __syncthreads();
        for (int off = 128; off > 0; off >>= 1) {
            if (t < off) { sa[t] += sa[t + off]; sb[t] += sb[t + off]; }
            __syncthreads();
        }
        if (t == 0) {
            // W * HUBER^2 = 25;  loss16 denom 64*2043*3;  loss32 denom 64*1019*3*4
            double l16 = 25.0 * sa[0] / 392256.0;
            double l32 = 25.0 * sb[0] / 782592.0;
            out[0] = (float)(l16 + l32);
            g_sync = 0;                        // reset for next graph replay
        }
    }
}

extern "C" void kernel_launch(void* const* d_in, const int* in_sizes, int n_in,
                              void* d_out, int out_size) {
    const float* w_hat = (const float*)d_in[0];
    const float* dw16  = (const float*)d_in[1];
    float* out = (float*)d_out;
    dg_loss_kernel<<<kBlocks, kThreads>>>(w_hat, dw16, out);
}

// round 3
// speedup vs baseline: 1.2673x; 1.0557x over previous
#include <cuda_runtime.h>

namespace {
constexpr int kGroups   = 131072;            // 64 * 2048
constexpr int kThreadsT = 2 * kGroups;       // 2 threads per group
constexpr int kThreads  = 256;
constexpr int kBlocks   = kThreadsT / kThreads;  // 2048? no: 262144/256 = 1024
constexpr float kDT = 0.005f;
}

// [0..kBlocks-1] = per-block sum16 partials, [kBlocks..2*kBlocks-1] = sum32
__device__ double g_partials[2 * kBlocks];
__device__ unsigned int g_sync = 0;

// Hamilton product: R(a (x) b) = R(a) R(b)
__device__ __forceinline__ void qmul(float aw, float ax, float ay, float az,
                                     float bw, float bx, float by, float bz,
                                     float& w, float& x, float& y, float& z) {
    w = aw*bw - ax*bx - ay*by - az*bz;
    x = aw*bx + ax*bw + ay*bz - az*by;
    y = aw*by - ax*bz + ay*bw + az*bx;
    z = aw*bz + ax*by - ay*bx + az*bw;
}

// exp of a SMALL rotation vector (|phi| <= ~0.05) as a unit quaternion.
// Even-polynomial in |phi|^2: no sqrt, no sincos, no branch; err ~1e-12.
__device__ __forceinline__ void exp_quat_small(float px, float py, float pz,
                                               float& w, float& x, float& y, float& z) {
    float n2 = fmaf(px, px, fmaf(py, py, pz * pz));
    float h2 = 0.25f * n2;                       // (|phi|/2)^2
    w = 1.0f + h2 * (-0.5f + h2 * (1.0f / 24.0f));
    float s = 0.5f + h2 * (-1.0f / 12.0f + h2 * (1.0f / 240.0f)); // sin(h)/|phi|
    x = s * px; y = s * py; z = s * pz;
}

// rs = log( R(a)^T R(b) );  returns sum_k SmoothL1(rs_k / HUBER)
__device__ __forceinline__ float log_huber_q(float aw, float ax, float ay, float az,
                                             float bw, float bx, float by, float bz) {
    float w = aw*bw + ax*bx + ay*by + az*bz;     // conj(a) (x) b
    float x = aw*bx - ax*bw - ay*bz + az*by;
    float y = aw*by + ax*bz - ay*bw - az*bx;
    float z = aw*bz - ax*by + ay*bx - az*bw;
    if (w < 0.0f) { w = -w; x = -x; y = -y; z = -z; }
    float n2 = fmaf(x, x, fmaf(y, y, z * z));
    float n  = sqrtf(n2);
    float ang = 2.0f * atan2f(n, w);             // [0, pi]
    float coef = ang / fmaxf(n, 1e-20f);
    float r0 = coef * x, r1 = coef * y, r2 = coef * z;

    float sum = 0.0f;
#pragma unroll
    for (int k = 0; k < 3; k++) {
        float r = (k == 0) ? r0 : ((k == 1) ? r1 : r2);
        float xx = r * 200.0f;                   // / HUBER
        float axv = fabsf(xx);
        sum += (axv < 1.0f) ? (0.5f * xx * xx) : (axv - 0.5f);
    }
    return sum;
}

__global__ void __launch_bounds__(kThreads)
dg_loss_kernel(const float* __restrict__ w_hat, const float* __restrict__ dw16,
               float* __restrict__ out) {
    const int t    = blockIdx.x * kThreads + threadIdx.x;  // 0 .. 262143
    const int m    = t >> 1;                               // group id
    const int g    = m & 2047;                             // group index in batch row
    const int half = t & 1;                                // which 8-sample half

    // ---- compose THIS thread's 8 increments (24 floats = 6 x LDG.128) ----
    const float4* base = reinterpret_cast<const float4*>(w_hat) + (size_t)t * 6;
    float qw, qx, qy, qz;
    {
        float f[24];
#pragma unroll
        for (int v = 0; v < 6; v++) {
            float4 q = base[v];
            f[4*v+0] = q.x; f[4*v+1] = q.y; f[4*v+2] = q.z; f[4*v+3] = q.w;
        }
        exp_quat_small(kDT * f[0], kDT * f[1], kDT * f[2], qw, qx, qy, qz);
#pragma unroll
        for (int i = 1; i < 8; i++) {
            float rw, rx, ry, rz;
            exp_quat_small(kDT * f[3*i+0], kDT * f[3*i+1], kDT * f[3*i+2], rw, rx, ry, rz);
            float tw, tx, ty, tz;
            qmul(qw, qx, qy, qz, rw, rx, ry, rz, tw, tx, ty, tz);
            qw = tw; qx = tx; qy = ty; qz = tz;
        }
    }

    // ---- combine halves via lane shuffle: full = lo (x) hi (bitwise identical on both lanes) ----
    {
        float pw = __shfl_xor_sync(0xFFFFFFFFu, qw, 1);
        float px = __shfl_xor_sync(0xFFFFFFFFu, qx, 1);
        float py = __shfl_xor_sync(0xFFFFFFFFu, qy, 1);
        float pz = __shfl_xor_sync(0xFFFFFFFFu, qz, 1);
        float aw = half ? pw : qw, ax = half ? px : qx,
              ay = half ? py : qy, az = half ? pz : qz;
        float bw = half ? qw : pw, bx = half ? qx : px,
              by = half ? qy : py, bz = half ? qz : pz;
        qmul(aw, ax, ay, az, bw, bx, by, bz, qw, qx, qy, qz);
    }

    // ---- ground-truth increment: even lanes only ----
    float pw = 1.0f, px = 0.0f, py = 0.0f, pz = 0.0f;
    float s16 = 0.0f;
    if (half == 0) {
        float4 d = reinterpret_cast<const float4*>(dw16)[(size_t)m * 12];
        float n2 = fmaf(d.x, d.x, fmaf(d.y, d.y, d.z * d.z));
        float th = sqrtf(n2);
        float s, c;
        sincosf(0.5f * th, &s, &c);
        float k = (th > 1e-7f) ? (s / th) : 0.5f;
        pw = c; px = k * d.x; py = k * d.y; pz = k * d.z;
        if (g >= 5) s16 = log_huber_q(qw, qx, qy, qz, pw, px, py, pz);
    }

    // ---- 32-level: groups m and m^1 live on lanes t and t^2 ----
    float qwP = __shfl_xor_sync(0xFFFFFFFFu, qw, 2);
    float qxP = __shfl_xor_sync(0xFFFFFFFFu, qx, 2);
    float qyP = __shfl_xor_sync(0xFFFFFFFFu, qy, 2);
    float qzP = __shfl_xor_sync(0xFFFFFFFFu, qz, 2);
    float pwP = __shfl_xor_sync(0xFFFFFFFFu, pw, 2);
    float pxP = __shfl_xor_sync(0xFFFFFFFFu, px, 2);
    float pyP = __shfl_xor_sync(0xFFFFFFFFu, py, 2);
    float pzP = __shfl_xor_sync(0xFFFFFFFFu, pz, 2);

    float s32 = 0.0f;
    if (half == 0 && ((g & 1) == 0) && g >= 10) {
        float hw, hx, hy, hz, gw, gx, gy, gz;
        qmul(qw, qx, qy, qz, qwP, qxP, qyP, qzP, hw, hx, hy, hz);   // hat pair
        qmul(pw, px, py, pz, pwP, pxP, pyP, pzP, gw, gx, gy, gz);   // gt pair
        s32 = log_huber_q(hw, hx, hy, hz, gw, gx, gy, gz);
    }

    // ---- deterministic block reduction ----
#pragma unroll
    for (int off = 16; off > 0; off >>= 1) {
        s16 += __shfl_down_sync(0xFFFFFFFFu, s16, off);
        s32 += __shfl_down_sync(0xFFFFFFFFu, s32, off);
    }
    __shared__ float w16[kThreads / 32], w32[kThreads / 32];
    __shared__ double sa[kThreads], sb[kThreads];
    __shared__ bool isLast;
    int lane = threadIdx.x & 31, wid = threadIdx.x >> 5;
    if (lane == 0) { w16[wid] = s16; w32[wid] = s32; }
    __syncthreads();
    if (threadIdx.x == 0) {
        float a = 0.0f, b = 0.0f;
#pragma unroll
        for (int i = 0; i < kThreads / 32; i++) { a += w16[i]; b += w32[i]; }
        g_partials[blockIdx.x] = (double)a;
        g_partials[kBlocks + blockIdx.x] = (double)b;
        __threadfence();
        unsigned prev = atomicAdd(&g_sync, 1u);
        isLast = (prev == (unsigned)(kBlocks - 1));
    }
    __syncthreads();

    // ---- last block: fixed-order final sum => deterministic ----
    if (isLast) {
        __threadfence();
        int tt = threadIdx.x;
        double a = 0.0, b = 0.0;
#pragma unroll
        for (int j = 0; j < kBlocks / kThreads; j++) {
            a += g_partials[tt + j * kThreads];
            b += g_partials[kBlocks + tt + j * kThreads];
        }
        sa[tt] = a; sb[tt] = b;
        __syncthreads();
        for (int off = 128; off > 0; off >>= 1) {
            if (tt < off) { sa[tt] += sa[tt + off]; sb[tt] += sb[tt + off]; }
            __syncthreads();
        }
        if (tt == 0) {
            // W * HUBER^2 = 25;  loss16 denom 64*2043*3;  loss32 denom 64*1019*3*4
            double l16 = 25.0 * sa[0] / 392256.0;
            double l32 = 25.0 * sb[0] / 782592.0;
            out[0] = (float)(l16 + l32);
            g_sync = 0;                         // reset for next graph replay
        }
    }
}

extern "C" void kernel_launch(void* const* d_in, const int* in_sizes, int n_in,
                              void* d_out, int out_size) {
    const float* w_hat = (const float*)d_in[0];
    const float* dw16  = (const float*)d_in[1];
    float* out = (float*)d_out;
    dg_loss_kernel<<<kBlocks, kThreads>>>(w_hat, dw16, out);
}

// round 4
// speedup vs baseline: 1.4590x; 1.1513x over previous
#include <cuda_runtime.h>

namespace {
constexpr int kGroups   = 131072;                 // 64 * 2048
constexpr int kThreadsT = 2 * kGroups;            // 2 threads per group
constexpr int kThreads  = 256;
constexpr int kBlocks   = kThreadsT / kThreads;   // 1024
constexpr float kDT = 0.005f;
}

// [0..kBlocks-1] = per-block sum16, [kBlocks..2*kBlocks-1] = sum32
__device__ double g_partials[2 * kBlocks];
__device__ unsigned int g_sync = 0;

// Hamilton product: R(a (x) b) = R(a) R(b)
__device__ __forceinline__ void qmul(float aw, float ax, float ay, float az,
                                     float bw, float bx, float by, float bz,
                                     float& w, float& x, float& y, float& z) {
    w = aw*bw - ax*bx - ay*by - az*bz;
    x = aw*bx + ax*bw + ay*bz - az*by;
    y = aw*by - ax*bz + ay*bw + az*bx;
    z = aw*bz + ax*by - ay*bx + az*bw;
}

// exp of a SMALL rotation vector (|phi| <= ~0.05): even-poly, branch-free.
__device__ __forceinline__ void exp_quat_small(float px, float py, float pz,
                                               float& w, float& x, float& y, float& z) {
    float n2 = fmaf(px, px, fmaf(py, py, pz * pz));
    float h2 = 0.25f * n2;                        // (|phi|/2)^2
    w = 1.0f + h2 * (-0.5f + h2 * (1.0f / 24.0f));
    float s = 0.5f + h2 * (-1.0f / 12.0f + h2 * (1.0f / 240.0f)); // sin(h)/|phi|
    x = s * px; y = s * py; z = s * pz;
}

// atan2(n, w) for n >= 0, w >= 0 (result in [0, pi/2]); ~1e-7 rad
__device__ __forceinline__ float atan2_pos(float n, float w) {
    bool swap = n > w;
    float num = swap ? w : n;
    float den = swap ? n : w;                     // den >= num >= 0, den > 0
    float q  = __fdividef(num, den);              // [0, 1]
    float q2 = q * q;
    float p =                     -0.0040540580734172f;
    p = fmaf(p, q2,  0.0218612288251226f);
    p = fmaf(p, q2, -0.0559098861838105f);
    p = fmaf(p, q2,  0.0964200441046623f);
    p = fmaf(p, q2, -0.1390853351676372f);
    p = fmaf(p, q2,  0.1994653599057577f);
    p = fmaf(p, q2, -0.3332985605689738f);
    p = fmaf(p, q2,  0.9999993329093277f);
    float a = p * q;
    return swap ? (1.5707963267948966f - a) : a;
}

// rs = log( R(a)^T R(b) );  returns sum_k SmoothL1(rs_k / HUBER)
__device__ __forceinline__ float log_huber_q(float aw, float ax, float ay, float az,
                                             float bw, float bx, float by, float bz) {
    float w = aw*bw + ax*bx + ay*by + az*bz;      // conj(a) (x) b
    float x = aw*bx - ax*bw - ay*bz + az*by;
    float y = aw*by + ax*bz - ay*bw - az*bx;
    float z = aw*bz - ax*by + ay*bx - az*bw;
    if (w < 0.0f) { w = -w; x = -x; y = -y; z = -z; }
    float n2 = fmaf(x, x, fmaf(y, y, z * z));
    float n  = sqrtf(n2);
    float ang = 2.0f * atan2_pos(n, w);           // [0, pi]
    float coef = __fdividef(ang, fmaxf(n, 1e-20f));
    float r0 = coef * x, r1 = coef * y, r2 = coef * z;

    float sum = 0.0f;
#pragma unroll
    for (int k = 0; k < 3; k++) {
        float r = (k == 0) ? r0 : ((k == 1) ? r1 : r2);
        float xx = r * 200.0f;                    // / HUBER
        float axv = fabsf(xx);
        sum += (axv < 1.0f) ? (0.5f * xx * xx) : (axv - 0.5f);
    }
    return sum;
}

__global__ void __launch_bounds__(kThreads)
dg_loss_kernel(const float* __restrict__ w_hat, const float* __restrict__ dw16,
               float* __restrict__ out) {
    const int t    = blockIdx.x * kThreads + threadIdx.x;  // 0 .. 262143
    const int m    = t >> 1;                               // group id
    const int g    = m & 2047;                             // group index in row
    const int half = t & 1;                                // which 8-sample half
    const bool mEven = (m & 1) == 0;

    // ---- compose THIS thread's 8 increments (24 floats = 6 x LDG.128) ----
    const float4* base = reinterpret_cast<const float4*>(w_hat) + (size_t)t * 6;
    float qw, qx, qy, qz;
    {
        // chunk A: floats 0..11
        float4 a0 = base[0], a1 = base[1], a2 = base[2];
        // chunk B issued early for MLP
        float4 b0 = base[3], b1 = base[4], b2 = base[5];

        float rw, rx, ry, rz, tw, tx, ty, tz;
        exp_quat_small(kDT * a0.x, kDT * a0.y, kDT * a0.z, qw, qx, qy, qz);
        exp_quat_small(kDT * a0.w, kDT * a1.x, kDT * a1.y, rw, rx, ry, rz);
        qmul(qw,qx,qy,qz, rw,rx,ry,rz, tw,tx,ty,tz); qw=tw;qx=tx;qy=ty;qz=tz;
        exp_quat_small(kDT * a1.z, kDT * a1.w, kDT * a2.x, rw, rx, ry, rz);
        qmul(qw,qx,qy,qz, rw,rx,ry,rz, tw,tx,ty,tz); qw=tw;qx=tx;qy=ty;qz=tz;
        exp_quat_small(kDT * a2.y, kDT * a2.z, kDT * a2.w, rw, rx, ry, rz);
        qmul(qw,qx,qy,qz, rw,rx,ry,rz, tw,tx,ty,tz); qw=tw;qx=tx;qy=ty;qz=tz;
        exp_quat_small(kDT * b0.x, kDT * b0.y, kDT * b0.z, rw, rx, ry, rz);
        qmul(qw,qx,qy,qz, rw,rx,ry,rz, tw,tx,ty,tz); qw=tw;qx=tx;qy=ty;qz=tz;
        exp_quat_small(kDT * b0.w, kDT * b1.x, kDT * b1.y, rw, rx, ry, rz);
        qmul(qw,qx,qy,qz, rw,rx,ry,rz, tw,tx,ty,tz); qw=tw;qx=tx;qy=ty;qz=tz;
        exp_quat_small(kDT * b1.z, kDT * b1.w, kDT * b2.x, rw, rx, ry, rz);
        qmul(qw,qx,qy,qz, rw,rx,ry,rz, tw,tx,ty,tz); qw=tw;qx=tx;qy=ty;qz=tz;
        exp_quat_small(kDT * b2.y, kDT * b2.z, kDT * b2.w, rw, rx, ry, rz);
        qmul(qw,qx,qy,qz, rw,rx,ry,rz, tw,tx,ty,tz); qw=tw;qx=tx;qy=ty;qz=tz;
    }

    // ---- combine halves: full = lo (x) hi (bitwise identical on both lanes) ----
    {
        float pw = __shfl_xor_sync(0xFFFFFFFFu, qw, 1);
        float px = __shfl_xor_sync(0xFFFFFFFFu, qx, 1);
        float py = __shfl_xor_sync(0xFFFFFFFFu, qy, 1);
        float pz = __shfl_xor_sync(0xFFFFFFFFu, qz, 1);
        float aw = half ? pw : qw, ax = half ? px : qx,
              ay = half ? py : qy, az = half ? pz : qz;
        float bw = half ? qw : pw, bx = half ? qx : px,
              by = half ? qy : py, bz = half ? qz : pz;
        qmul(aw, ax, ay, az, bw, bx, by, bz, qw, qx, qy, qz);
    }

    // ---- ground-truth increment for group m: ALL lanes (uniform, no divergence) ----
    float pw, px, py, pz;
    {
        float4 d = reinterpret_cast<const float4*>(dw16)[(size_t)m * 12];
        float n2 = fmaf(d.x, d.x, fmaf(d.y, d.y, d.z * d.z));
        float th = sqrtf(n2);
        float s, c;
        sincosf(0.5f * th, &s, &c);
        float k = (th > 1e-7f) ? __fdividef(s, th) : 0.5f;
        pw = c; px = k * d.x; py = k * d.y; pz = k * d.z;
    }

    // ---- exchange with partner group (m ^ 1): lanes t <-> t^2 ----
    float qwP = __shfl_xor_sync(0xFFFFFFFFu, qw, 2);
    float qxP = __shfl_xor_sync(0xFFFFFFFFu, qx, 2);
    float qyP = __shfl_xor_sync(0xFFFFFFFFu, qy, 2);
    float qzP = __shfl_xor_sync(0xFFFFFFFFu, qz, 2);
    float pwP = __shfl_xor_sync(0xFFFFFFFFu, pw, 2);
    float pxP = __shfl_xor_sync(0xFFFFFFFFu, px, 2);
    float pyP = __shfl_xor_sync(0xFFFFFFFFu, py, 2);
    float pzP = __shfl_xor_sync(0xFFFFFFFFu, pz, 2);

    // ---- ONE log/huber pass, lane-specialized ----
    // even lanes: 16-level (qhat_m vs gt_m)
    // lanes == 1 mod 4 (half==1, m even): 32-level pair (q_m(x)q_{m+1} vs gt_m(x)gt_{m+1})
    float Aw, Ax, Ay, Az, Bw, Bx, By, Bz;
    if (half == 0) {
        Aw = qw; Ax = qx; Ay = qy; Az = qz;
        Bw = pw; Bx = px; By = py; Bz = pz;
    } else {
        qmul(qw, qx, qy, qz, qwP, qxP, qyP, qzP, Aw, Ax, Ay, Az);  // hat pair
        qmul(pw, px, py, pz, pwP, pxP, pyP, pzP, Bw, Bx, By, Bz);  // gt pair
    }
    float val = log_huber_q(Aw, Ax, Ay, Az, Bw, Bx, By, Bz);

    float s16 = (half == 0 && g >= 5) ? val : 0.0f;
    float s32 = (half == 1 && mEven && g >= 10) ? val : 0.0f;

    // ---- deterministic block reduction ----
#pragma unroll
    for (int off = 16; off > 0; off >>= 1) {
        s16 += __shfl_down_sync(0xFFFFFFFFu, s16, off);
        s32 += __shfl_down_sync(0xFFFFFFFFu, s32, off);
    }
    __shared__ float w16[kThreads / 32], w32[kThreads / 32];
    __shared__ double sa[kThreads], sb[kThreads];
    __shared__ bool isLast;
    int lane = threadIdx.x & 31, wid = threadIdx.x >> 5;
    if (lane == 0) { w16[wid] = s16; w32[wid] = s32; }
    __syncthreads();
    if (threadIdx.x == 0) {
        float a = 0.0f, b = 0.0f;
#pragma unroll
        for (int i = 0; i < kThreads / 32; i++) { a += w16[i]; b += w32[i]; }
        g_partials[blockIdx.x] = (double)a;
        g_partials[kBlocks + blockIdx.x] = (double)b;
        __threadfence();
        unsigned prev = atomicAdd(&g_sync, 1u);
        isLast = (prev == (unsigned)(kBlocks - 1));
    }
    __syncthreads();

    // ---- last block: fixed-order final sum => deterministic ----
    if (isLast) {
        __threadfence();
        int tt = threadIdx.x;
        double a = 0.0, b = 0.0;
#pragma unroll
        for (int j = 0; j < kBlocks / kThreads; j++) {
            a += g_partials[tt + j * kThreads];
            b += g_partials[kBlocks + tt + j * kThreads];
        }
        sa[tt] = a; sb[tt] = b;
        __syncthreads();
        for (int off = 128; off > 0; off >>= 1) {
            if (tt < off) { sa[tt] += sa[tt + off]; sb[tt] += sb[tt + off]; }
            __syncthreads();
        }
        if (tt == 0) {
            // W * HUBER^2 = 25;  loss16 denom 64*2043*3;  loss32 denom 64*1019*3*4
            double l16 = 25.0 * sa[0] / 392256.0;
            double l32 = 25.0 * sb[0] / 782592.0;
            out[0] = (float)(l16 + l32);
            g_sync = 0;                          // reset for next graph replay
        }
    }
}

extern "C" void kernel_launch(void* const* d_in, const int* in_sizes, int n_in,
                              void* d_out, int out_size) {
    const float* w_hat = (const float*)d_in[0];
    const float* dw16  = (const float*)d_in[1];
    float* out = (float*)d_out;
    dg_loss_kernel<<<kBlocks, kThreads>>>(w_hat, dw16, out);
}